// round 4
// baseline (speedup 1.0000x reference)
#include <cuda_runtime.h>

#define K          84
#define CHUNKS     21          // K/4 (16B chunks per row)
#define NPROTO     10
#define THREADS    256
#define NWARPS     (THREADS / 32)
#define STAGE_ROWS 256
#define STAGE_FLOATS (STAGE_ROWS * K)        // 21504
#define STAGE_VEC4   (STAGE_FLOATS / 4)      // 5376
#define COPIES_PER_THREAD (STAGE_VEC4 / THREADS)  // 21
#define NPASS ((STAGE_ROWS + 2) / 3)         // 86 passes of 3 rows

// dynamic smem: buf[2][STAGE_FLOATS] + x2[STAGE_ROWS]
#define SMEM_BYTES (2 * STAGE_FLOATS * 4 + STAGE_ROWS * 4 + 64)

__device__ __forceinline__ void ffma2(unsigned long long &d,
                                      unsigned long long a,
                                      unsigned long long b) {
    asm("fma.rn.f32x2 %0, %1, %2, %0;" : "+l"(d) : "l"(a), "l"(b));
}
__device__ __forceinline__ float f2lo(unsigned long long v) {
    return __int_as_float((unsigned)(v & 0xffffffffULL));
}
__device__ __forceinline__ float f2hi(unsigned long long v) {
    return __int_as_float((unsigned)(v >> 32));
}
__device__ __forceinline__ void cp_async16(unsigned smem_addr, const void* gptr) {
    asm volatile("cp.async.cg.shared.global [%0], [%1], 16;\n"
                 :: "r"(smem_addr), "l"(gptr));
}
__device__ __forceinline__ void cp_commit() {
    asm volatile("cp.async.commit_group;\n" ::: "memory");
}
__device__ __forceinline__ void cp_wait1() {
    asm volatile("cp.async.wait_group 1;\n" ::: "memory");
}

__global__ void __launch_bounds__(THREADS, 1)
rbf_kernel(const float* __restrict__ x,
           const float* __restrict__ weight,
           float* __restrict__ out,
           int nrows) {
    extern __shared__ __align__(16) float smem[];
    float* s_buf0 = smem;                       // [STAGE_FLOATS]
    float* s_buf1 = smem + STAGE_FLOATS;        // [STAGE_FLOATS]
    float* s_x2   = smem + 2 * STAGE_FLOATS;    // [STAGE_ROWS]

    const int t    = threadIdx.x;
    const int lane = t & 31;
    const int wid  = t >> 5;

    const int proto   = lane % NPROTO;   // lanes 30,31 alias protos 0,1 (unused)
    const int row_off = lane / NPROTO;   // 0..2 valid, 3 for lanes 30,31
    const bool blane  = lane < 30;

    // ---- per-lane weights in registers (load once) ----
    ulonglong2 wreg[CHUNKS];
    {
        const ulonglong2* wp = (const ulonglong2*)(weight + proto * K);
        #pragma unroll
        for (int i = 0; i < CHUNKS; i++) wreg[i] = wp[i];
    }
    // ---- per-lane ||w||^2 ----
    float w2l;
    {
        unsigned long long a = 0ULL, b = 0ULL;
        #pragma unroll
        for (int i = 0; i < CHUNKS; i++) {
            ffma2(a, wreg[i].x, wreg[i].x);
            ffma2(b, wreg[i].y, wreg[i].y);
        }
        w2l = (f2lo(a) + f2hi(a)) + (f2lo(b) + f2hi(b));
    }

    const int nstages = (nrows + STAGE_ROWS - 1) / STAGE_ROWS;
    const int step = gridDim.x;
    int count = 0;
    for (long long s = blockIdx.x; s < nstages; s += step) count++;

    unsigned buf_addr[2];
    buf_addr[0] = (unsigned)__cvta_generic_to_shared(s_buf0);
    buf_addr[1] = (unsigned)__cvta_generic_to_shared(s_buf1);
    const float* bufs[2] = { s_buf0, s_buf1 };

    auto issue_stage = [&](int j) {
        long long stage = (long long)blockIdx.x + (long long)j * step;
        const float4* gx = (const float4*)x + stage * STAGE_VEC4;
        unsigned dst = buf_addr[j & 1] + t * 16;
        const float4* src = gx + t;
        long long remaining4 = ((long long)nrows * K) / 4 - stage * STAGE_VEC4;
        if (remaining4 >= STAGE_VEC4) {
            #pragma unroll
            for (int i = 0; i < COPIES_PER_THREAD; i++)
                cp_async16(dst + i * THREADS * 16, src + i * THREADS);
        } else {
            #pragma unroll
            for (int i = 0; i < COPIES_PER_THREAD; i++)
                if (i * THREADS + t < remaining4)
                    cp_async16(dst + i * THREADS * 16, src + i * THREADS);
        }
    };

    if (count > 0) issue_stage(0);
    cp_commit();
    if (count > 1) issue_stage(1);
    cp_commit();

    __syncthreads();

    for (int j = 0; j < count; j++) {
        cp_wait1();
        __syncthreads();

        const long long stage = (long long)blockIdx.x + (long long)j * step;
        const float* sx = bufs[j & 1];

        // ---- phase A: x2[row] for this stage (1 row per thread) ----
        {
            const ulonglong2* rp = (const ulonglong2*)(sx + t * K);
            unsigned long long a0 = 0ULL, a1 = 0ULL, a2 = 0ULL, a3 = 0ULL;
            #pragma unroll
            for (int c = 0; c < CHUNKS; c++) {
                ulonglong2 v = rp[c];
                if (c & 1) { ffma2(a2, v.x, v.x); ffma2(a3, v.y, v.y); }
                else       { ffma2(a0, v.x, v.x); ffma2(a1, v.y, v.y); }
            }
            float s = (f2lo(a0) + f2hi(a0)) + (f2lo(a1) + f2hi(a1))
                    + (f2lo(a2) + f2hi(a2)) + (f2lo(a3) + f2hi(a3));
            s_x2[t] = s;
        }
        __syncthreads();

        // ---- phase B: dot products, weights in regs, rows broadcast ----
        if (blane) {
            const long long grow_base = stage * STAGE_ROWS;
            for (int p = wid; p < NPASS; p += NWARPS) {
                int r = 3 * p + row_off;
                int rc = (r < STAGE_ROWS) ? r : (STAGE_ROWS - 1);
                const ulonglong2* rp = (const ulonglong2*)(sx + rc * K);
                unsigned long long a0 = 0ULL, a1 = 0ULL, a2 = 0ULL, a3 = 0ULL;
                #pragma unroll
                for (int c = 0; c < CHUNKS; c++) {
                    ulonglong2 v = rp[c];
                    if (c & 1) { ffma2(a2, v.x, wreg[c].x); ffma2(a3, v.y, wreg[c].y); }
                    else       { ffma2(a0, v.x, wreg[c].x); ffma2(a1, v.y, wreg[c].y); }
                }
                float dot = (f2lo(a0) + f2hi(a0)) + (f2lo(a1) + f2hi(a1))
                          + (f2lo(a2) + f2hi(a2)) + (f2lo(a3) + f2hi(a3));
                float res = fmaf(-2.f, dot, s_x2[rc] + w2l);
                long long grow = grow_base + r;
                if (r < STAGE_ROWS && grow < (long long)nrows)
                    out[grow * NPROTO + proto] = res;
            }
        }

        __syncthreads();                 // buffer j%2 fully consumed
        if (j + 2 < count) issue_stage(j + 2);
        cp_commit();
    }
}

extern "C" void kernel_launch(void* const* d_in, const int* in_sizes, int n_in,
                              void* d_out, int out_size) {
    const float* x = (const float*)d_in[0];
    const float* w = (const float*)d_in[1];
    float* out = (float*)d_out;

    const int nrows = in_sizes[0] / K;   // 524288

    static int nsm = 0;
    if (nsm == 0) {
        cudaFuncSetAttribute(rbf_kernel,
                             cudaFuncAttributeMaxDynamicSharedMemorySize,
                             SMEM_BYTES);
        cudaDeviceGetAttribute(&nsm, cudaDevAttrMultiProcessorCount, 0);
        if (nsm <= 0) nsm = 148;
    }

    rbf_kernel<<<nsm, THREADS, SMEM_BYTES>>>(x, w, out, nrows);
}

// round 5
// speedup vs baseline: 1.8982x; 1.8982x over previous
#include <cuda_runtime.h>

#define K          84
#define CHUNKS     21          // K/4 (16B chunks per row)
#define NPROTO     10
#define THREADS    128
#define STAGE_ROWS 128         // 1 row per thread
#define STAGE_FLOATS (STAGE_ROWS * K)        // 10752
#define STAGE_VEC4   (STAGE_FLOATS / 4)      // 2688
#define COPIES_PER_THREAD (STAGE_VEC4 / THREADS)  // 21

// dynamic smem per CTA:
//   buf[2][STAGE_FLOATS]                  2 * 43008 B
//   wblk[CHUNKS*NPROTO] ulonglong2        210 * 16 B = 3360 B
//   w2[16] floats                         64 B
// total 89440 B  -> 2 CTAs / SM
#define SMEM_BYTES (2 * STAGE_FLOATS * 4 + CHUNKS * NPROTO * 16 + 64)

__device__ __forceinline__ void ffma2(unsigned long long &d,
                                      unsigned long long a,
                                      unsigned long long b) {
    asm("fma.rn.f32x2 %0, %1, %2, %0;" : "+l"(d) : "l"(a), "l"(b));
}
__device__ __forceinline__ float f2lo(unsigned long long v) {
    return __int_as_float((unsigned)(v & 0xffffffffULL));
}
__device__ __forceinline__ float f2hi(unsigned long long v) {
    return __int_as_float((unsigned)(v >> 32));
}
__device__ __forceinline__ void cp_async16(unsigned smem_addr, const void* gptr) {
    asm volatile("cp.async.cg.shared.global [%0], [%1], 16;\n"
                 :: "r"(smem_addr), "l"(gptr));
}
__device__ __forceinline__ void cp_commit() {
    asm volatile("cp.async.commit_group;\n" ::: "memory");
}
__device__ __forceinline__ void cp_wait1() {
    asm volatile("cp.async.wait_group 1;\n" ::: "memory");
}

__global__ void __launch_bounds__(THREADS, 2)
rbf_kernel(const float* __restrict__ x,
           const float* __restrict__ weight,
           float* __restrict__ out,
           int nrows) {
    extern __shared__ __align__(16) float smem[];
    float* s_buf0 = smem;                                 // [STAGE_FLOATS]
    float* s_buf1 = smem + STAGE_FLOATS;                  // [STAGE_FLOATS]
    ulonglong2* s_w = (ulonglong2*)(smem + 2 * STAGE_FLOATS); // [CHUNKS*NPROTO]
    float* s_w2 = (float*)(s_w + CHUNKS * NPROTO);        // [16]

    const int t = threadIdx.x;

    // ---- build weight blocks: s_w[c*10+k] = chunk c of proto k ----
    for (int i = t; i < CHUNKS * NPROTO; i += THREADS) {
        int c = i / NPROTO;
        int k = i - c * NPROTO;
        const float4 v = *(const float4*)(weight + k * K + 4 * c);
        ulonglong2 u;
        u.x = ((unsigned long long)__float_as_uint(v.y) << 32) | __float_as_uint(v.x);
        u.y = ((unsigned long long)__float_as_uint(v.w) << 32) | __float_as_uint(v.z);
        s_w[i] = u;
    }
    if (t < NPROTO) {
        float s = 0.f;
        #pragma unroll
        for (int j = 0; j < K; j++) { float w = weight[t * K + j]; s += w * w; }
        s_w2[t] = s;
    }

    const int nstages = (nrows + STAGE_ROWS - 1) / STAGE_ROWS;  // 4096
    const int step = gridDim.x;
    int count = 0;
    for (long long s = blockIdx.x; s < nstages; s += step) count++;

    unsigned buf_addr[2];
    buf_addr[0] = (unsigned)__cvta_generic_to_shared(s_buf0);
    buf_addr[1] = (unsigned)__cvta_generic_to_shared(s_buf1);
    const float* bufs[2] = { s_buf0, s_buf1 };

    auto issue_stage = [&](int j) {
        long long stage = (long long)blockIdx.x + (long long)j * step;
        const float4* gx = (const float4*)x + stage * STAGE_VEC4;
        unsigned dst = buf_addr[j & 1] + t * 16;
        const float4* src = gx + t;
        long long remaining4 = ((long long)nrows * K) / 4 - stage * STAGE_VEC4;
        if (remaining4 >= STAGE_VEC4) {
            #pragma unroll
            for (int i = 0; i < COPIES_PER_THREAD; i++)
                cp_async16(dst + i * THREADS * 16, src + i * THREADS);
        } else {
            #pragma unroll
            for (int i = 0; i < COPIES_PER_THREAD; i++)
                if (i * THREADS + t < remaining4)
                    cp_async16(dst + i * THREADS * 16, src + i * THREADS);
        }
    };

    // ---- pipeline prologue ----
    if (count > 0) issue_stage(0);
    cp_commit();
    if (count > 1) issue_stage(1);
    cp_commit();

    __syncthreads();   // also covers s_w / s_w2 init

    for (int j = 0; j < count; j++) {
        cp_wait1();
        __syncthreads();

        const long long stage = (long long)blockIdx.x + (long long)j * step;
        const float* sx = bufs[j & 1];

        const ulonglong2* rowA = (const ulonglong2*)(sx + t * K);

        unsigned long long acc[NPROTO];
        unsigned long long x2a = 0ULL;
        #pragma unroll
        for (int k = 0; k < NPROTO; k++) acc[k] = 0ULL;

        #pragma unroll
        for (int c = 0; c < CHUNKS; c++) {
            ulonglong2 va = rowA[c];
            ffma2(x2a, va.x, va.x);
            ffma2(x2a, va.y, va.y);
            #pragma unroll
            for (int k = 0; k < NPROTO; k++) {
                ulonglong2 wv = s_w[c * NPROTO + k];
                ffma2(acc[k], va.x, wv.x);
                ffma2(acc[k], va.y, wv.y);
            }
        }

        float x2A = f2lo(x2a) + f2hi(x2a);

        const long long rA = stage * STAGE_ROWS + t;
        if (rA < nrows) {
            float2* o = (float2*)(out + rA * NPROTO);
            #pragma unroll
            for (int k = 0; k < 5; k++) {
                float w2a = s_w2[2 * k], w2b = s_w2[2 * k + 1];
                o[k] = make_float2(
                    fmaf(-2.f, f2lo(acc[2 * k])     + f2hi(acc[2 * k]),     x2A + w2a),
                    fmaf(-2.f, f2lo(acc[2 * k + 1]) + f2hi(acc[2 * k + 1]), x2A + w2b));
            }
        }

        __syncthreads();                 // buffer j%2 fully consumed
        if (j + 2 < count) issue_stage(j + 2);
        cp_commit();
    }
}

extern "C" void kernel_launch(void* const* d_in, const int* in_sizes, int n_in,
                              void* d_out, int out_size) {
    const float* x = (const float*)d_in[0];
    const float* w = (const float*)d_in[1];
    float* out = (float*)d_out;

    const int nrows = in_sizes[0] / K;   // 524288

    static int nsm = 0;
    if (nsm == 0) {
        cudaFuncSetAttribute(rbf_kernel,
                             cudaFuncAttributeMaxDynamicSharedMemorySize,
                             SMEM_BYTES);
        cudaDeviceGetAttribute(&nsm, cudaDevAttrMultiProcessorCount, 0);
        if (nsm <= 0) nsm = 148;
    }

    // 2 CTAs per SM — independent sync domains on each scheduler
    rbf_kernel<<<2 * nsm, THREADS, SMEM_BYTES>>>(x, w, out, nrows);
}